// round 2
// baseline (speedup 1.0000x reference)
#include <cuda_runtime.h>
#include <math.h>

#define BQ 8
#define HH 56
#define WW 56
#define LL 3136          // HH*WW
#define BL 25088         // BQ*LL
#define DMODEL 384
#define DINNER 768
#define NH 12
#define HD 64
#define DST 64
#define CONVD 896        // DINNER + 2*DSTATE
#define DPROJ 1676       // 2*DINNER + 2*DSTATE + NH

// ---------------- scratch (device globals: allocation-free contract) ----------------
__device__ float g_z[(size_t)BL * DINNER];      // z branch
__device__ float g_xBC[(size_t)BL * CONVD];     // pre-conv xBC
__device__ float g_dt[(size_t)BL * NH];         // softplus(dt + bias)
__device__ float g_xBCa[(size_t)BL * CONVD];    // post conv+silu  (xs | B | C)
__device__ float g_dx[(size_t)BL * DINNER];     // dt*A*xs ; later reused as y
__device__ float g_dxp[(size_t)BL * DINNER];    // pooled dx
__device__ float g_hstate[BQ * NH * DST * HD];  // per (b,h) 64x64 state
__device__ float g_gn[(size_t)BL * DINNER];     // post-LN activations

// ---------------- generic 64x64 tile GEMM:  C[m,n] = sum_k A[m,k] * Bw[n,k] ----------------
// MODE 0: A = x, N = DPROJ, epilogue splits into z / xBC / softplus(dt)
// MODE 1: A = g_gn, N = DMODEL, epilogue writes out[m*N+n]
template <int KDIM, int MODE>
__global__ void __launch_bounds__(256) gemm64_kernel(
    const float* __restrict__ A, const float* __restrict__ Bw,
    float* __restrict__ out, const float* __restrict__ dt_bias, int N)
{
    __shared__ __align__(16) float As[16][68];
    __shared__ __align__(16) float Bs[16][68];

    const int bm = blockIdx.y * 64;
    const int bn = blockIdx.x * 64;
    const int tid = threadIdx.x;
    const int ty = tid >> 4;
    const int tx = tid & 15;

    const float* Ap = (MODE == 0) ? A : g_gn;

    float acc[4][4];
#pragma unroll
    for (int i = 0; i < 4; i++)
#pragma unroll
        for (int j = 0; j < 4; j++) acc[i][j] = 0.f;

    const int lm = tid >> 2;           // 0..63  (row within tile)
    const int lk = (tid & 3) * 4;      // 0,4,8,12 (k offset)

    for (int k0 = 0; k0 < KDIM; k0 += 16) {
        float4 va = *(const float4*)(Ap + (size_t)(bm + lm) * KDIM + k0 + lk);
        float4 vb = make_float4(0.f, 0.f, 0.f, 0.f);
        if (bn + lm < N)
            vb = *(const float4*)(Bw + (size_t)(bn + lm) * KDIM + k0 + lk);
        As[lk + 0][lm] = va.x; As[lk + 1][lm] = va.y;
        As[lk + 2][lm] = va.z; As[lk + 3][lm] = va.w;
        Bs[lk + 0][lm] = vb.x; Bs[lk + 1][lm] = vb.y;
        Bs[lk + 2][lm] = vb.z; Bs[lk + 3][lm] = vb.w;
        __syncthreads();
#pragma unroll
        for (int kk = 0; kk < 16; kk++) {
            float4 a = *(const float4*)&As[kk][ty * 4];
            float4 b = *(const float4*)&Bs[kk][tx * 4];
            float av[4] = {a.x, a.y, a.z, a.w};
            float bv[4] = {b.x, b.y, b.z, b.w};
#pragma unroll
            for (int i = 0; i < 4; i++)
#pragma unroll
                for (int j = 0; j < 4; j++)
                    acc[i][j] = fmaf(av[i], bv[j], acc[i][j]);
        }
        __syncthreads();
    }

#pragma unroll
    for (int i = 0; i < 4; i++) {
        const int m = bm + ty * 4 + i;
#pragma unroll
        for (int j = 0; j < 4; j++) {
            const int n = bn + tx * 4 + j;
            const float v = acc[i][j];
            if (MODE == 1) {
                out[(size_t)m * DMODEL + n] = v;
            } else {
                if (n < DINNER) {
                    g_z[(size_t)m * DINNER + n] = v;
                } else if (n < DINNER + CONVD) {
                    g_xBC[(size_t)m * CONVD + (n - DINNER)] = v;
                } else if (n < DPROJ) {
                    const int h = n - (DINNER + CONVD);
                    const float t = v + dt_bias[h];
                    g_dt[(size_t)m * NH + h] = (t > 20.f) ? t : log1pf(expf(t));
                }
            }
        }
    }
}

// ---------------- depthwise 3x3 conv + bias + silu, fused dx = silu(conv) * dt * (-exp(A_log)) ----
__global__ void __launch_bounds__(128) conv_kernel(
    const float* __restrict__ cw, const float* __restrict__ cb,
    const float* __restrict__ A_log)
{
    const int c = blockIdx.y * 128 + threadIdx.x;   // 0..895
    const int bl = blockIdx.x;
    const int b = bl / LL;
    const int l = bl - b * LL;
    const int y = l / WW;
    const int x = l - y * WW;

    float acc = cb[c];
#pragma unroll
    for (int dy = -1; dy <= 1; dy++) {
        const int yy = y + dy;
        if (yy < 0 || yy >= HH) continue;
#pragma unroll
        for (int dx = -1; dx <= 1; dx++) {
            const int xx = x + dx;
            if (xx < 0 || xx >= WW) continue;
            acc = fmaf(g_xBC[((size_t)(b * LL + yy * WW + xx)) * CONVD + c],
                       cw[c * 9 + (dy + 1) * 3 + (dx + 1)], acc);
        }
    }
    const float act = acc / (1.f + expf(-acc));     // silu
    g_xBCa[(size_t)bl * CONVD + c] = act;
    if (c < DINNER) {
        const int h = c >> 6;
        const float dxv = act * g_dt[(size_t)bl * NH + h] * (-expf(A_log[c]));
        g_dx[(size_t)bl * DINNER + c] = dxv;
    }
}

// ---------------- 3x3 count-normalized average pool over spatial dims ----------------
__global__ void __launch_bounds__(128) pool_kernel()
{
    const int c = blockIdx.y * 128 + threadIdx.x;   // 0..767
    const int bl = blockIdx.x;
    const int b = bl / LL;
    const int l = bl - b * LL;
    const int y = l / WW;
    const int x = l - y * WW;

    const int y0 = max(y - 1, 0), y1 = min(y + 1, HH - 1);
    const int x0 = max(x - 1, 0), x1 = min(x + 1, WW - 1);
    float s = 0.f;
    for (int yy = y0; yy <= y1; yy++)
        for (int xx = x0; xx <= x1; xx++)
            s += g_dx[((size_t)(b * LL + yy * WW + xx)) * DINNER + c];
    const float inv = 1.f / (float)((y1 - y0 + 1) * (x1 - x0 + 1));
    g_dxp[(size_t)bl * DINNER + c] = s * inv;
}

// ---------------- zero h_state ----------------
__global__ void zero_hstate()
{
    const int i = blockIdx.x * 256 + threadIdx.x;   // 98304 float4 total
    ((float4*)g_hstate)[i] = make_float4(0.f, 0.f, 0.f, 0.f);
}

// ---------------- h_state[b,h,s,d] += sum_l B[b,l,s] * dxp[b,l,h,d]   (split-K over L) ----
__global__ void __launch_bounds__(256) hstate_kernel()
{
    const int b = blockIdx.z;
    const int h = blockIdx.y;
    const int l0 = blockIdx.x * 448;

    __shared__ __align__(16) float Bs[16][64];
    __shared__ __align__(16) float Ds[16][64];

    const int tid = threadIdx.x;
    const int ty = tid >> 4, tx = tid & 15;
    const int lr = tid >> 4;
    const int f4 = (tid & 15) * 4;

    float acc[4][4];
#pragma unroll
    for (int i = 0; i < 4; i++)
#pragma unroll
        for (int j = 0; j < 4; j++) acc[i][j] = 0.f;

    for (int lt = 0; lt < 448; lt += 16) {
        const int l = l0 + lt + lr;
        const size_t rb = (size_t)(b * LL + l);
        *(float4*)&Bs[lr][f4] = *(const float4*)(g_xBCa + rb * CONVD + DINNER + f4);
        *(float4*)&Ds[lr][f4] = *(const float4*)(g_dxp + rb * DINNER + h * HD + f4);
        __syncthreads();
#pragma unroll
        for (int kk = 0; kk < 16; kk++) {
            float4 a = *(const float4*)&Bs[kk][ty * 4];
            float4 d = *(const float4*)&Ds[kk][tx * 4];
            float av[4] = {a.x, a.y, a.z, a.w};
            float dv[4] = {d.x, d.y, d.z, d.w};
#pragma unroll
            for (int i = 0; i < 4; i++)
#pragma unroll
                for (int j = 0; j < 4; j++)
                    acc[i][j] = fmaf(av[i], dv[j], acc[i][j]);
        }
        __syncthreads();
    }

    float* hp = g_hstate + (size_t)(b * NH + h) * DST * HD;
#pragma unroll
    for (int i = 0; i < 4; i++)
#pragma unroll
        for (int j = 0; j < 4; j++)
            atomicAdd(&hp[(ty * 4 + i) * HD + tx * 4 + j], acc[i][j]);
}

// ---------------- y[b,l,h,d] = sum_s C[b,l,s]*hstate[b,h,s,d] + xs * D[h]  (writes into g_dx) ----
__global__ void __launch_bounds__(256) ch_kernel(const float* __restrict__ Dp)
{
    const int b = blockIdx.z;
    const int h = blockIdx.y;
    const int l0 = blockIdx.x * 64;

    __shared__ __align__(16) float Hs[64][64];   // [s][d]
    __shared__ __align__(16) float Cs[64][68];   // [s][l] (transposed)

    const int tid = threadIdx.x;
    const int ty = tid >> 4, tx = tid & 15;

    // load hstate slab (4096 floats = 1024 float4)
    {
        const float4* hsrc = (const float4*)(g_hstate + (size_t)(b * NH + h) * DST * HD);
        float4* hdst = (float4*)Hs;
#pragma unroll
        for (int i = 0; i < 4; i++) hdst[tid + i * 256] = hsrc[tid + i * 256];
    }
    // load + transpose C tile: rows l0..l0+63, ALL 64 s values each.
    // 4 threads per row; each thread loads 4 float4s at s = base, base+16, base+32, base+48.
    {
        const int lr = tid >> 2;
        const int base = (tid & 3) * 4;
        const float* crow = g_xBCa + (size_t)(b * LL + l0 + lr) * CONVD + DINNER + DST;
#pragma unroll
        for (int it = 0; it < 4; it++) {
            const int sq = base + it * 16;
            float4 v = *(const float4*)(crow + sq);
            Cs[sq + 0][lr] = v.x; Cs[sq + 1][lr] = v.y;
            Cs[sq + 2][lr] = v.z; Cs[sq + 3][lr] = v.w;
        }
    }
    __syncthreads();

    float acc[4][4];
#pragma unroll
    for (int i = 0; i < 4; i++)
#pragma unroll
        for (int j = 0; j < 4; j++) acc[i][j] = 0.f;

#pragma unroll 16
    for (int s = 0; s < 64; s++) {
        float4 a = *(const float4*)&Cs[s][ty * 4];
        float4 hv = *(const float4*)&Hs[s][tx * 4];
        float av[4] = {a.x, a.y, a.z, a.w};
        float hvv[4] = {hv.x, hv.y, hv.z, hv.w};
#pragma unroll
        for (int i = 0; i < 4; i++)
#pragma unroll
            for (int j = 0; j < 4; j++)
                acc[i][j] = fmaf(av[i], hvv[j], acc[i][j]);
    }

    const float dcoef = Dp[h];
#pragma unroll
    for (int i = 0; i < 4; i++) {
        const int l = l0 + ty * 4 + i;
        const size_t r = (size_t)(b * LL + l);
#pragma unroll
        for (int j = 0; j < 4; j++) {
            const int d = tx * 4 + j;
            const int c = h * HD + d;
            const float xs = g_xBCa[r * CONVD + c];
            g_dx[r * DINNER + c] = acc[i][j] + xs * dcoef;  // y
        }
    }
}

// ---------------- g = y * silu(z); LayerNorm -> g_gn ----------------
__global__ void __launch_bounds__(256) ln_kernel(
    const float* __restrict__ nw, const float* __restrict__ nb)
{
    const int bl = blockIdx.x;
    const int tid = threadIdx.x;
    __shared__ float smu[8], sv[8];

    float v[3];
    float s = 0.f, s2 = 0.f;
#pragma unroll
    for (int i = 0; i < 3; i++) {
        const int c = tid + i * 256;
        const float y = g_dx[(size_t)bl * DINNER + c];
        const float z = g_z[(size_t)bl * DINNER + c];
        const float gg = y * (z / (1.f + expf(-z)));
        v[i] = gg;
        s += gg;
        s2 += gg * gg;
    }
#pragma unroll
    for (int o = 16; o > 0; o >>= 1) {
        s += __shfl_xor_sync(0xffffffffu, s, o);
        s2 += __shfl_xor_sync(0xffffffffu, s2, o);
    }
    const int w = tid >> 5;
    if ((tid & 31) == 0) { smu[w] = s; sv[w] = s2; }
    __syncthreads();
    float ts = 0.f, ts2 = 0.f;
#pragma unroll
    for (int i = 0; i < 8; i++) { ts += smu[i]; ts2 += sv[i]; }

    const float mu = ts * (1.f / (float)DINNER);
    const float var = ts2 * (1.f / (float)DINNER) - mu * mu;
    const float rstd = rsqrtf(var + 1e-5f);
#pragma unroll
    for (int i = 0; i < 3; i++) {
        const int c = tid + i * 256;
        g_gn[(size_t)bl * DINNER + c] = (v[i] - mu) * rstd * nw[c] + nb[c];
    }
}

// ---------------- launch ----------------
extern "C" void kernel_launch(void* const* d_in, const int* in_sizes, int n_in,
                              void* d_out, int out_size)
{
    const float* x    = (const float*)d_in[0];   // [BL, 384]
    const float* win  = (const float*)d_in[1];   // [1676, 384]
    const float* cw   = (const float*)d_in[2];   // [896, 1, 3, 3]
    const float* cb   = (const float*)d_in[3];   // [896]
    const float* dtb  = (const float*)d_in[4];   // [12]
    const float* alog = (const float*)d_in[5];   // [768]
    const float* Dp   = (const float*)d_in[6];   // [12]
    const float* nw   = (const float*)d_in[7];   // [768]
    const float* nb   = (const float*)d_in[8];   // [768]
    const float* wout = (const float*)d_in[9];   // [384, 768]
    float* out = (float*)d_out;                  // [BL, 384]

    // 1) in-proj GEMM + split (z / xBC / softplus-dt)
    gemm64_kernel<DMODEL, 0><<<dim3(27, 392), 256>>>(x, win, nullptr, dtb, DPROJ);
    // 2) depthwise conv + silu, fused dx = act * dt * (-exp(A_log))
    conv_kernel<<<dim3(BL, 7), 128>>>(cw, cb, alog);
    // 3) 3x3 count-normalized avg pool
    pool_kernel<<<dim3(BL, 6), 128>>>();
    // 4) zero h_state, 5) split-K batched state GEMM
    zero_hstate<<<384, 256>>>();
    hstate_kernel<<<dim3(7, 12, 8), 256>>>();
    // 6) Ch + D*x -> y
    ch_kernel<<<dim3(49, 12, 8), 256>>>(Dp);
    // 7) gate + LayerNorm
    ln_kernel<<<BL, 256>>>(nw, nb);
    // 8) out-proj GEMM
    gemm64_kernel<DINNER, 1><<<dim3(6, 392), 256>>>(nullptr, wout, out, nullptr, DMODEL);
}

// round 3
// speedup vs baseline: 1.7661x; 1.7661x over previous
#include <cuda_runtime.h>
#include <math.h>
#include <stdint.h>

#define BQ 8
#define HH 56
#define WW 56
#define LL 3136          // HH*WW
#define BL 25088         // BQ*LL
#define DMODEL 384
#define DINNER 768
#define NH 12
#define HD 64
#define DST 64
#define CONVD 896        // DINNER + 2*DSTATE
#define DPROJ 1676       // 2*DINNER + 2*DSTATE + NH

// ---------------- scratch (device globals: allocation-free contract) ----------------
__device__ float g_z[(size_t)BL * DINNER];      // z branch
__device__ float g_xBC[(size_t)BL * CONVD];     // pre-conv xBC
__device__ float g_dt[(size_t)BL * NH];         // softplus(dt + bias)
__device__ float g_xBCa[(size_t)BL * CONVD];    // post conv+silu  (xs | B | C)
__device__ float g_dx[(size_t)BL * DINNER];     // dt*A*xs ; later reused as y
__device__ float g_dxp[(size_t)BL * DINNER];    // pooled dx
__device__ float g_hstate[BQ * NH * DST * HD];  // per (b,h) 64x64 state
__device__ float g_gn[(size_t)BL * DINNER];     // post-LN activations

__device__ __forceinline__ uint32_t f2tf32(float f) {
    uint32_t u;
    asm("cvt.rna.tf32.f32 %0, %1;" : "=r"(u) : "f"(f));
    return u;
}

__device__ __forceinline__ void mma_tf32(float c[4], uint32_t a0, uint32_t a1,
                                         uint32_t a2, uint32_t a3,
                                         uint32_t b0, uint32_t b1) {
    asm volatile(
        "mma.sync.aligned.m16n8k8.row.col.f32.tf32.tf32.f32 "
        "{%0,%1,%2,%3}, {%4,%5,%6,%7}, {%8,%9}, {%0,%1,%2,%3};"
        : "+f"(c[0]), "+f"(c[1]), "+f"(c[2]), "+f"(c[3])
        : "r"(a0), "r"(a1), "r"(a2), "r"(a3), "r"(b0), "r"(b1));
}

// ---------------- tf32 tensor-core GEMM:  C[m,n] = sum_k A[m,k] * Bw[n,k] ----------------
// Tiles: 128x128x16, 256 threads = 8 warps in 2x4 grid, warp tile 64x32 (4x4 m16n8k8 frags).
// MODE 0: A = x, N = DPROJ, epilogue splits into z / xBC / softplus(dt)
// MODE 1: A = g_gn, N = DMODEL, epilogue writes out
#define SMPAD 136   // row stride: bank = (8k + m) % 32, conflict-free fragment LDS
template <int KDIM, int MODE>
__global__ void __launch_bounds__(256) gemm_tc_kernel(
    const float* __restrict__ A, const float* __restrict__ Bw,
    float* __restrict__ out, const float* __restrict__ dt_bias, int N)
{
    __shared__ float As[2][16][SMPAD];
    __shared__ float Bs[2][16][SMPAD];

    const int bm = blockIdx.y * 128;
    const int bn = blockIdx.x * 128;
    const int tid = threadIdx.x;
    const int lane = tid & 31;
    const int warp = tid >> 5;
    const int wm = (warp >> 2) * 64;   // 0 / 64
    const int wn = (warp & 3) * 32;    // 0 / 32 / 64 / 96

    const float* Ap = (MODE == 0) ? A : g_gn;

    // global-load mapping: each thread owns 2 rows (passes), 4 contiguous k each
    const int rowL = tid >> 2;          // 0..63
    const int kq = (tid & 3) * 4;       // 0,4,8,12

    float acc[4][4][4];
#pragma unroll
    for (int i = 0; i < 4; i++)
#pragma unroll
        for (int j = 0; j < 4; j++)
#pragma unroll
            for (int r = 0; r < 4; r++) acc[i][j][r] = 0.f;

    float4 ra[2], rb[2];

    // ---- tile load (LDG) ----
    auto load_tile = [&](int kt) {
        const int k0 = kt * 16 + kq;
#pragma unroll
        for (int p = 0; p < 2; p++) {
            const int ma = bm + rowL + p * 64;
            ra[p] = *(const float4*)(Ap + (size_t)ma * KDIM + k0);
            const int nb = bn + rowL + p * 64;
            if (MODE == 1 || nb < N)
                rb[p] = *(const float4*)(Bw + (size_t)nb * KDIM + k0);
            else
                rb[p] = make_float4(0.f, 0.f, 0.f, 0.f);
        }
    };
    // ---- tile store (cvt to tf32 + STS transposed to [k][m]) ----
    auto store_tile = [&](int buf) {
#pragma unroll
        for (int p = 0; p < 2; p++) {
            const int m = rowL + p * 64;
            float av[4] = {ra[p].x, ra[p].y, ra[p].z, ra[p].w};
            float bv[4] = {rb[p].x, rb[p].y, rb[p].z, rb[p].w};
#pragma unroll
            for (int q = 0; q < 4; q++) {
                As[buf][kq + q][m] = __uint_as_float(f2tf32(av[q]));
                Bs[buf][kq + q][m] = __uint_as_float(f2tf32(bv[q]));
            }
        }
    };
    // ---- compute one 16-deep k tile ----
    auto compute = [&](int buf) {
#pragma unroll
        for (int ks = 0; ks < 2; ks++) {
            const int kb = ks * 8 + (lane & 3);
            uint32_t bf[4][2];
#pragma unroll
            for (int j = 0; j < 4; j++) {
                const int n = wn + j * 8 + (lane >> 2);
                bf[j][0] = __float_as_uint(Bs[buf][kb][n]);
                bf[j][1] = __float_as_uint(Bs[buf][kb + 4][n]);
            }
#pragma unroll
            for (int i = 0; i < 4; i++) {
                const int m = wm + i * 16 + (lane >> 2);
                uint32_t a0 = __float_as_uint(As[buf][kb][m]);
                uint32_t a1 = __float_as_uint(As[buf][kb][m + 8]);
                uint32_t a2 = __float_as_uint(As[buf][kb + 4][m]);
                uint32_t a3 = __float_as_uint(As[buf][kb + 4][m + 8]);
#pragma unroll
                for (int j = 0; j < 4; j++)
                    mma_tf32(acc[i][j], a0, a1, a2, a3, bf[j][0], bf[j][1]);
            }
        }
    };

    constexpr int KT = KDIM / 16;
    load_tile(0);
    store_tile(0);
    __syncthreads();
#pragma unroll 1
    for (int kt = 0; kt < KT; kt++) {
        if (kt + 1 < KT) load_tile(kt + 1);
        compute(kt & 1);
        if (kt + 1 < KT) store_tile((kt + 1) & 1);
        __syncthreads();
    }

    // ---- epilogue ----
#pragma unroll
    for (int i = 0; i < 4; i++) {
#pragma unroll
        for (int j = 0; j < 4; j++) {
#pragma unroll
            for (int r = 0; r < 4; r++) {
                const int m = bm + wm + i * 16 + (lane >> 2) + (r >> 1) * 8;
                const int n = bn + wn + j * 8 + (lane & 3) * 2 + (r & 1);
                const float v = acc[i][j][r];
                if (MODE == 1) {
                    out[(size_t)m * DMODEL + n] = v;
                } else {
                    if (n < DINNER) {
                        g_z[(size_t)m * DINNER + n] = v;
                    } else if (n < DINNER + CONVD) {
                        g_xBC[(size_t)m * CONVD + (n - DINNER)] = v;
                    } else if (n < DPROJ) {
                        const int h = n - (DINNER + CONVD);
                        const float t = v + dt_bias[h];
                        g_dt[(size_t)m * NH + h] = (t > 20.f) ? t : log1pf(expf(t));
                    }
                }
            }
        }
    }
}

// ---------------- depthwise 3x3 conv + bias + silu, fused dx = silu(conv) * dt * (-exp(A_log)) ----
__global__ void __launch_bounds__(128) conv_kernel(
    const float* __restrict__ cw, const float* __restrict__ cb,
    const float* __restrict__ A_log)
{
    const int c = blockIdx.y * 128 + threadIdx.x;   // 0..895
    const int bl = blockIdx.x;
    const int b = bl / LL;
    const int l = bl - b * LL;
    const int y = l / WW;
    const int x = l - y * WW;

    float acc = cb[c];
#pragma unroll
    for (int dy = -1; dy <= 1; dy++) {
        const int yy = y + dy;
        if (yy < 0 || yy >= HH) continue;
#pragma unroll
        for (int dx = -1; dx <= 1; dx++) {
            const int xx = x + dx;
            if (xx < 0 || xx >= WW) continue;
            acc = fmaf(g_xBC[((size_t)(b * LL + yy * WW + xx)) * CONVD + c],
                       cw[c * 9 + (dy + 1) * 3 + (dx + 1)], acc);
        }
    }
    const float act = acc / (1.f + expf(-acc));     // silu
    g_xBCa[(size_t)bl * CONVD + c] = act;
    if (c < DINNER) {
        const int h = c >> 6;
        const float dxv = act * g_dt[(size_t)bl * NH + h] * (-expf(A_log[c]));
        g_dx[(size_t)bl * DINNER + c] = dxv;
    }
}

// ---------------- 3x3 count-normalized average pool over spatial dims ----------------
__global__ void __launch_bounds__(128) pool_kernel()
{
    const int c = blockIdx.y * 128 + threadIdx.x;   // 0..767
    const int bl = blockIdx.x;
    const int b = bl / LL;
    const int l = bl - b * LL;
    const int y = l / WW;
    const int x = l - y * WW;

    const int y0 = max(y - 1, 0), y1 = min(y + 1, HH - 1);
    const int x0 = max(x - 1, 0), x1 = min(x + 1, WW - 1);
    float s = 0.f;
    for (int yy = y0; yy <= y1; yy++)
        for (int xx = x0; xx <= x1; xx++)
            s += g_dx[((size_t)(b * LL + yy * WW + xx)) * DINNER + c];
    const float inv = 1.f / (float)((y1 - y0 + 1) * (x1 - x0 + 1));
    g_dxp[(size_t)bl * DINNER + c] = s * inv;
}

// ---------------- zero h_state ----------------
__global__ void zero_hstate()
{
    const int i = blockIdx.x * 256 + threadIdx.x;   // 98304 float4 total
    ((float4*)g_hstate)[i] = make_float4(0.f, 0.f, 0.f, 0.f);
}

// ---------------- h_state[b,h,s,d] += sum_l B[b,l,s] * dxp[b,l,h,d]   (split-K over L) ----
__global__ void __launch_bounds__(256) hstate_kernel()
{
    const int b = blockIdx.z;
    const int h = blockIdx.y;
    const int l0 = blockIdx.x * 448;

    __shared__ __align__(16) float Bs[16][64];
    __shared__ __align__(16) float Ds[16][64];

    const int tid = threadIdx.x;
    const int ty = tid >> 4, tx = tid & 15;
    const int lr = tid >> 4;
    const int f4 = (tid & 15) * 4;

    float acc[4][4];
#pragma unroll
    for (int i = 0; i < 4; i++)
#pragma unroll
        for (int j = 0; j < 4; j++) acc[i][j] = 0.f;

    for (int lt = 0; lt < 448; lt += 16) {
        const int l = l0 + lt + lr;
        const size_t rb = (size_t)(b * LL + l);
        *(float4*)&Bs[lr][f4] = *(const float4*)(g_xBCa + rb * CONVD + DINNER + f4);
        *(float4*)&Ds[lr][f4] = *(const float4*)(g_dxp + rb * DINNER + h * HD + f4);
        __syncthreads();
#pragma unroll
        for (int kk = 0; kk < 16; kk++) {
            float4 a = *(const float4*)&Bs[kk][ty * 4];
            float4 d = *(const float4*)&Ds[kk][tx * 4];
            float av[4] = {a.x, a.y, a.z, a.w};
            float dv[4] = {d.x, d.y, d.z, d.w};
#pragma unroll
            for (int i = 0; i < 4; i++)
#pragma unroll
                for (int j = 0; j < 4; j++)
                    acc[i][j] = fmaf(av[i], dv[j], acc[i][j]);
        }
        __syncthreads();
    }

    float* hp = g_hstate + (size_t)(b * NH + h) * DST * HD;
#pragma unroll
    for (int i = 0; i < 4; i++)
#pragma unroll
        for (int j = 0; j < 4; j++)
            atomicAdd(&hp[(ty * 4 + i) * HD + tx * 4 + j], acc[i][j]);
}

// ---------------- y[b,l,h,d] = sum_s C[b,l,s]*hstate[b,h,s,d] + xs * D[h]  (writes into g_dx) ----
__global__ void __launch_bounds__(256) ch_kernel(const float* __restrict__ Dp)
{
    const int b = blockIdx.z;
    const int h = blockIdx.y;
    const int l0 = blockIdx.x * 64;

    __shared__ __align__(16) float Hs[64][64];   // [s][d]
    __shared__ __align__(16) float Cs[64][68];   // [s][l] (transposed)

    const int tid = threadIdx.x;
    const int ty = tid >> 4, tx = tid & 15;

    // load hstate slab (4096 floats = 1024 float4)
    {
        const float4* hsrc = (const float4*)(g_hstate + (size_t)(b * NH + h) * DST * HD);
        float4* hdst = (float4*)Hs;
#pragma unroll
        for (int i = 0; i < 4; i++) hdst[tid + i * 256] = hsrc[tid + i * 256];
    }
    // load + transpose C tile: rows l0..l0+63, ALL 64 s values each.
    {
        const int lr = tid >> 2;
        const int base = (tid & 3) * 4;
        const float* crow = g_xBCa + (size_t)(b * LL + l0 + lr) * CONVD + DINNER + DST;
#pragma unroll
        for (int it = 0; it < 4; it++) {
            const int sq = base + it * 16;
            float4 v = *(const float4*)(crow + sq);
            Cs[sq + 0][lr] = v.x; Cs[sq + 1][lr] = v.y;
            Cs[sq + 2][lr] = v.z; Cs[sq + 3][lr] = v.w;
        }
    }
    __syncthreads();

    float acc[4][4];
#pragma unroll
    for (int i = 0; i < 4; i++)
#pragma unroll
        for (int j = 0; j < 4; j++) acc[i][j] = 0.f;

#pragma unroll 16
    for (int s = 0; s < 64; s++) {
        float4 a = *(const float4*)&Cs[s][ty * 4];
        float4 hv = *(const float4*)&Hs[s][tx * 4];
        float av[4] = {a.x, a.y, a.z, a.w};
        float hvv[4] = {hv.x, hv.y, hv.z, hv.w};
#pragma unroll
        for (int i = 0; i < 4; i++)
#pragma unroll
            for (int j = 0; j < 4; j++)
                acc[i][j] = fmaf(av[i], hvv[j], acc[i][j]);
    }

    const float dcoef = Dp[h];
#pragma unroll
    for (int i = 0; i < 4; i++) {
        const int l = l0 + ty * 4 + i;
        const size_t r = (size_t)(b * LL + l);
#pragma unroll
        for (int j = 0; j < 4; j++) {
            const int d = tx * 4 + j;
            const int c = h * HD + d;
            const float xs = g_xBCa[r * CONVD + c];
            g_dx[r * DINNER + c] = acc[i][j] + xs * dcoef;  // y
        }
    }
}

// ---------------- g = y * silu(z); LayerNorm -> g_gn ----------------
__global__ void __launch_bounds__(256) ln_kernel(
    const float* __restrict__ nw, const float* __restrict__ nb)
{
    const int bl = blockIdx.x;
    const int tid = threadIdx.x;
    __shared__ float smu[8], sv[8];

    float v[3];
    float s = 0.f, s2 = 0.f;
#pragma unroll
    for (int i = 0; i < 3; i++) {
        const int c = tid + i * 256;
        const float y = g_dx[(size_t)bl * DINNER + c];
        const float z = g_z[(size_t)bl * DINNER + c];
        const float gg = y * (z / (1.f + expf(-z)));
        v[i] = gg;
        s += gg;
        s2 += gg * gg;
    }
#pragma unroll
    for (int o = 16; o > 0; o >>= 1) {
        s += __shfl_xor_sync(0xffffffffu, s, o);
        s2 += __shfl_xor_sync(0xffffffffu, s2, o);
    }
    const int w = tid >> 5;
    if ((tid & 31) == 0) { smu[w] = s; sv[w] = s2; }
    __syncthreads();
    float ts = 0.f, ts2 = 0.f;
#pragma unroll
    for (int i = 0; i < 8; i++) { ts += smu[i]; ts2 += sv[i]; }

    const float mu = ts * (1.f / (float)DINNER);
    const float var = ts2 * (1.f / (float)DINNER) - mu * mu;
    const float rstd = rsqrtf(var + 1e-5f);
#pragma unroll
    for (int i = 0; i < 3; i++) {
        const int c = tid + i * 256;
        g_gn[(size_t)bl * DINNER + c] = (v[i] - mu) * rstd * nw[c] + nb[c];
    }
}

// ---------------- launch ----------------
extern "C" void kernel_launch(void* const* d_in, const int* in_sizes, int n_in,
                              void* d_out, int out_size)
{
    const float* x    = (const float*)d_in[0];   // [BL, 384]
    const float* win  = (const float*)d_in[1];   // [1676, 384]
    const float* cw   = (const float*)d_in[2];   // [896, 1, 3, 3]
    const float* cb   = (const float*)d_in[3];   // [896]
    const float* dtb  = (const float*)d_in[4];   // [12]
    const float* alog = (const float*)d_in[5];   // [768]
    const float* Dp   = (const float*)d_in[6];   // [12]
    const float* nw   = (const float*)d_in[7];   // [768]
    const float* nb   = (const float*)d_in[8];   // [768]
    const float* wout = (const float*)d_in[9];   // [384, 768]
    float* out = (float*)d_out;                  // [BL, 384]

    // 1) in-proj GEMM (tf32 tensor cores) + split (z / xBC / softplus-dt)
    gemm_tc_kernel<DMODEL, 0><<<dim3(14, 196), 256>>>(x, win, nullptr, dtb, DPROJ);
    // 2) depthwise conv + silu, fused dx = act * dt * (-exp(A_log))
    conv_kernel<<<dim3(BL, 7), 128>>>(cw, cb, alog);
    // 3) 3x3 count-normalized avg pool
    pool_kernel<<<dim3(BL, 6), 128>>>();
    // 4) zero h_state, 5) split-K batched state GEMM
    zero_hstate<<<384, 256>>>();
    hstate_kernel<<<dim3(7, 12, 8), 256>>>();
    // 6) Ch + D*x -> y
    ch_kernel<<<dim3(49, 12, 8), 256>>>(Dp);
    // 7) gate + LayerNorm
    ln_kernel<<<BL, 256>>>(nw, nb);
    // 8) out-proj GEMM (tf32 tensor cores)
    gemm_tc_kernel<DINNER, 1><<<dim3(3, 196), 256>>>(nullptr, wout, out, nullptr, DMODEL);
}

// round 5
// speedup vs baseline: 2.0001x; 1.1325x over previous
#include <cuda_runtime.h>
#include <math.h>
#include <stdint.h>

#define BQ 8
#define HH 56
#define WW 56
#define LL 3136          // HH*WW
#define BL 25088         // BQ*LL
#define DMODEL 384
#define DINNER 768
#define NH 12
#define HD 64
#define DST 64
#define CONVD 896        // DINNER + 2*DSTATE
#define DPROJ 1676       // 2*DINNER + 2*DSTATE + NH

// ---------------- scratch (device globals: allocation-free contract) ----------------
__device__ float g_z[(size_t)BL * DINNER];      // z branch
__device__ float g_xBC[(size_t)BL * CONVD];     // pre-conv xBC
__device__ float g_dt[(size_t)BL * NH];         // softplus(dt + bias)
__device__ float g_xBCa[(size_t)BL * CONVD];    // post conv+silu  (xs | B | C)
__device__ float g_dx[(size_t)BL * DINNER];     // dt*A*xs ; later reused as y
__device__ float g_dxp[(size_t)BL * DINNER];    // pooled dx
__device__ float g_hstate[BQ * NH * DST * HD];  // per (b,h) 64x64 state
__device__ float g_gn[(size_t)BL * DINNER];     // post-LN activations (tf32-rounded)
__device__ float g_xcvt[(size_t)BL * DMODEL];   // tf32-rounded x
__device__ float g_wincvt[(size_t)DPROJ * DMODEL];   // tf32-rounded in_proj_w
__device__ float g_woutcvt[(size_t)DMODEL * DINNER]; // tf32-rounded out_proj_w

__device__ __forceinline__ uint32_t f2tf32(float f) {
    uint32_t u;
    asm("cvt.rna.tf32.f32 %0, %1;" : "=r"(u) : "f"(f));
    return u;
}
__device__ __forceinline__ uint32_t smem_u32(const void* p) {
    uint32_t a;
    asm("{ .reg .u64 t; cvta.to.shared.u64 t, %1; cvt.u32.u64 %0, t; }"
        : "=r"(a) : "l"(p));
    return a;
}
__device__ __forceinline__ void mma_tf32(float c[4], uint32_t a0, uint32_t a1,
                                         uint32_t a2, uint32_t a3,
                                         uint32_t b0, uint32_t b1) {
    asm volatile(
        "mma.sync.aligned.m16n8k8.row.col.f32.tf32.tf32.f32 "
        "{%0,%1,%2,%3}, {%4,%5,%6,%7}, {%8,%9}, {%0,%1,%2,%3};"
        : "+f"(c[0]), "+f"(c[1]), "+f"(c[2]), "+f"(c[3])
        : "r"(a0), "r"(a1), "r"(a2), "r"(a3), "r"(b0), "r"(b1));
}
__device__ __forceinline__ void cpa16(uint32_t dst, const void* src, int srcbytes) {
    asm volatile("cp.async.cg.shared.global [%0], [%1], 16, %2;"
                 :: "r"(dst), "l"(src), "r"(srcbytes) : "memory");
}
__device__ __forceinline__ void cpa_commit() {
    asm volatile("cp.async.commit_group;" ::: "memory");
}
__device__ __forceinline__ void cpa_wait2() {
    asm volatile("cp.async.wait_group 2;" ::: "memory");
}

// ---------------- tf32-round elementwise convert (float4 granularity) ----------------
__global__ void __launch_bounds__(256) cvt_kernel(
    const float* __restrict__ src, float* __restrict__ dst, int n4)
{
    const int i = blockIdx.x * 256 + threadIdx.x;
    if (i < n4) {
        float4 v = ((const float4*)src)[i];
        uint4 t;
        t.x = f2tf32(v.x); t.y = f2tf32(v.y);
        t.z = f2tf32(v.z); t.w = f2tf32(v.w);
        ((uint4*)dst)[i] = t;
    }
}

// ============ tf32 mma.sync GEMM, cp.async 4-stage pipeline ============
// C[m,n] = sum_k A[m,k] * Bw[n,k]. CTA tile 128x128, k-tile 16, 256 thr = 8 warps
// (2x4), warp tile 64x32 = 4x4 m16n8k8 frags. Inputs pre-rounded to tf32.
// MODE 0: A = g_xcvt, Bw = g_wincvt, N = DPROJ, split epilogue
// MODE 1: A = g_gn,  Bw = g_woutcvt, N = DMODEL, plain store
#define ROWF 20                       // floats per smem row (16 data + 4 pad)
#define STAGEB (128 * ROWF * 4)       // 10240 bytes per matrix per stage
#define GSTAGES 4
#define GEMM_DSMEM (2 * GSTAGES * STAGEB + 128)

template <int KDIM, int MODE>
__global__ void __launch_bounds__(256) gemm_mma(
    float* __restrict__ out, const float* __restrict__ dt_bias, int N)
{
    extern __shared__ char raw_smem[];
    const uint32_t raw_u = smem_u32(raw_smem);
    const uint32_t dsm_u = (raw_u + 127u) & ~127u;
    char* dsm = raw_smem + (dsm_u - raw_u);

    const int tid = threadIdx.x;
    const int lane = tid & 31;
    const int warp = tid >> 5;
    const int bm = blockIdx.y * 128;
    const int bn = blockIdx.x * 128;
    const int wm = (warp >> 2) * 64;
    const int wn = (warp & 3) * 32;

    const float* Ap = (MODE == 0) ? g_xcvt : g_gn;
    const float* Bp = (MODE == 0) ? g_wincvt : g_woutcvt;

    float acc[4][4][4];
#pragma unroll
    for (int i = 0; i < 4; i++)
#pragma unroll
        for (int j = 0; j < 4; j++)
#pragma unroll
            for (int r = 0; r < 4; r++) acc[i][j][r] = 0.f;

    // loader mapping: 512 float4 chunks per matrix per stage; 2 per thread
    // chunk c: row = c>>2 (0..127), q = c&3 (16B slot within 16-float row)
    auto issue_stage = [&](int kt, int s) {
        const int k0 = kt * 16;
        const uint32_t abase = dsm_u + s * STAGEB;
        const uint32_t bbase = dsm_u + GSTAGES * STAGEB + s * STAGEB;
#pragma unroll
        for (int i = 0; i < 2; i++) {
            const int c = tid + i * 256;
            const int row = c >> 2;
            const int q = c & 3;
            const uint32_t soff = (uint32_t)(row * ROWF + q * 4) * 4;
            cpa16(abase + soff, Ap + (size_t)(bm + row) * KDIM + k0 + q * 4, 16);
            const int nb = bn + row;
            const int okB = (MODE == 1 || nb < N) ? 16 : 0;
            // clamp row so OOB src addr stays in-bounds (srcbytes=0 -> zero fill)
            const int nbs = (MODE == 1 || nb < N) ? nb : (N - 1);
            cpa16(bbase + soff, Bp + (size_t)nbs * KDIM + k0 + q * 4, okB);
        }
    };

    constexpr int KT = KDIM / 16;
    // prologue
#pragma unroll
    for (int p = 0; p < GSTAGES - 1; p++) {
        issue_stage(p, p);
        cpa_commit();
    }

#pragma unroll 1
    for (int kt = 0; kt < KT; kt++) {
        const int s = kt & (GSTAGES - 1);
        cpa_wait2();
        __syncthreads();

        const float* Asb = (const float*)(dsm + s * STAGEB);
        const float* Bsb = (const float*)(dsm + GSTAGES * STAGEB + s * STAGEB);
#pragma unroll
        for (int ks = 0; ks < 2; ks++) {
            const int kb = ks * 8 + (lane & 3);
            uint32_t bf[4][2];
#pragma unroll
            for (int j = 0; j < 4; j++) {
                const int n = wn + j * 8 + (lane >> 2);
                bf[j][0] = __float_as_uint(Bsb[n * ROWF + kb]);
                bf[j][1] = __float_as_uint(Bsb[n * ROWF + kb + 4]);
            }
#pragma unroll
            for (int i = 0; i < 4; i++) {
                const int m = wm + i * 16 + (lane >> 2);
                uint32_t a0 = __float_as_uint(Asb[m * ROWF + kb]);
                uint32_t a1 = __float_as_uint(Asb[(m + 8) * ROWF + kb]);
                uint32_t a2 = __float_as_uint(Asb[m * ROWF + kb + 4]);
                uint32_t a3 = __float_as_uint(Asb[(m + 8) * ROWF + kb + 4]);
#pragma unroll
                for (int j = 0; j < 4; j++)
                    mma_tf32(acc[i][j], a0, a1, a2, a3, bf[j][0], bf[j][1]);
            }
        }

        const int nk = kt + GSTAGES - 1;
        if (nk < KT) issue_stage(nk, nk & (GSTAGES - 1));
        cpa_commit();
    }

    // ---- epilogue (same fragment->global mapping as validated R3) ----
#pragma unroll
    for (int i = 0; i < 4; i++) {
#pragma unroll
        for (int j = 0; j < 4; j++) {
#pragma unroll
            for (int r = 0; r < 4; r++) {
                const int m = bm + wm + i * 16 + (lane >> 2) + (r >> 1) * 8;
                const int n = bn + wn + j * 8 + (lane & 3) * 2 + (r & 1);
                const float v = acc[i][j][r];
                if (MODE == 1) {
                    out[(size_t)m * DMODEL + n] = v;
                } else {
                    if (n < DINNER) {
                        g_z[(size_t)m * DINNER + n] = v;
                    } else if (n < DINNER + CONVD) {
                        g_xBC[(size_t)m * CONVD + (n - DINNER)] = v;
                    } else if (n < DPROJ) {
                        const int h = n - (DINNER + CONVD);
                        const float t = v + dt_bias[h];
                        g_dt[(size_t)m * NH + h] = (t > 20.f) ? t : log1pf(expf(t));
                    }
                }
            }
        }
    }
}

// ---------------- depthwise 3x3 conv + bias + silu, fused dx = silu(conv) * dt * (-exp(A_log)) ----
__global__ void __launch_bounds__(128) conv_kernel(
    const float* __restrict__ cw, const float* __restrict__ cb,
    const float* __restrict__ A_log)
{
    const int c = blockIdx.y * 128 + threadIdx.x;   // 0..895
    const int bl = blockIdx.x;
    const int b = bl / LL;
    const int l = bl - b * LL;
    const int y = l / WW;
    const int x = l - y * WW;

    float acc = cb[c];
#pragma unroll
    for (int dy = -1; dy <= 1; dy++) {
        const int yy = y + dy;
        if (yy < 0 || yy >= HH) continue;
#pragma unroll
        for (int dx = -1; dx <= 1; dx++) {
            const int xx = x + dx;
            if (xx < 0 || xx >= WW) continue;
            acc = fmaf(g_xBC[((size_t)(b * LL + yy * WW + xx)) * CONVD + c],
                       cw[c * 9 + (dy + 1) * 3 + (dx + 1)], acc);
        }
    }
    const float act = acc / (1.f + expf(-acc));     // silu
    g_xBCa[(size_t)bl * CONVD + c] = act;
    if (c < DINNER) {
        const int h = c >> 6;
        const float dxv = act * g_dt[(size_t)bl * NH + h] * (-expf(A_log[c]));
        g_dx[(size_t)bl * DINNER + c] = dxv;
    }
}

// ---------------- 3x3 count-normalized average pool over spatial dims ----------------
__global__ void __launch_bounds__(128) pool_kernel()
{
    const int c = blockIdx.y * 128 + threadIdx.x;   // 0..767
    const int bl = blockIdx.x;
    const int b = bl / LL;
    const int l = bl - b * LL;
    const int y = l / WW;
    const int x = l - y * WW;

    const int y0 = max(y - 1, 0), y1 = min(y + 1, HH - 1);
    const int x0 = max(x - 1, 0), x1 = min(x + 1, WW - 1);
    float s = 0.f;
    for (int yy = y0; yy <= y1; yy++)
        for (int xx = x0; xx <= x1; xx++)
            s += g_dx[((size_t)(b * LL + yy * WW + xx)) * DINNER + c];
    const float inv = 1.f / (float)((y1 - y0 + 1) * (x1 - x0 + 1));
    g_dxp[(size_t)bl * DINNER + c] = s * inv;
}

// ---------------- zero h_state ----------------
__global__ void zero_hstate()
{
    const int i = blockIdx.x * 256 + threadIdx.x;
    ((float4*)g_hstate)[i] = make_float4(0.f, 0.f, 0.f, 0.f);
}

// ---------------- h_state[b,h,s,d] += sum_l B[b,l,s] * dxp[b,l,h,d]   (split-K over L) ----
__global__ void __launch_bounds__(256) hstate_kernel()
{
    const int b = blockIdx.z;
    const int h = blockIdx.y;
    const int l0 = blockIdx.x * 448;

    __shared__ __align__(16) float Bs[16][64];
    __shared__ __align__(16) float Ds[16][64];

    const int tid = threadIdx.x;
    const int ty = tid >> 4, tx = tid & 15;
    const int lr = tid >> 4;
    const int f4 = (tid & 15) * 4;

    float acc[4][4];
#pragma unroll
    for (int i = 0; i < 4; i++)
#pragma unroll
        for (int j = 0; j < 4; j++) acc[i][j] = 0.f;

    for (int lt = 0; lt < 448; lt += 16) {
        const int l = l0 + lt + lr;
        const size_t rb = (size_t)(b * LL + l);
        *(float4*)&Bs[lr][f4] = *(const float4*)(g_xBCa + rb * CONVD + DINNER + f4);
        *(float4*)&Ds[lr][f4] = *(const float4*)(g_dxp + rb * DINNER + h * HD + f4);
        __syncthreads();
#pragma unroll
        for (int kk = 0; kk < 16; kk++) {
            float4 a = *(const float4*)&Bs[kk][ty * 4];
            float4 d = *(const float4*)&Ds[kk][tx * 4];
            float av[4] = {a.x, a.y, a.z, a.w};
            float dv[4] = {d.x, d.y, d.z, d.w};
#pragma unroll
            for (int i = 0; i < 4; i++)
#pragma unroll
                for (int j = 0; j < 4; j++)
                    acc[i][j] = fmaf(av[i], dv[j], acc[i][j]);
        }
        __syncthreads();
    }

    float* hp = g_hstate + (size_t)(b * NH + h) * DST * HD;
#pragma unroll
    for (int i = 0; i < 4; i++)
#pragma unroll
        for (int j = 0; j < 4; j++)
            atomicAdd(&hp[(ty * 4 + i) * HD + tx * 4 + j], acc[i][j]);
}

// ---------------- y[b,l,h,d] = sum_s C[b,l,s]*hstate[b,h,s,d] + xs * D[h]  (writes into g_dx) ----
__global__ void __launch_bounds__(256) ch_kernel(const float* __restrict__ Dp)
{
    const int b = blockIdx.z;
    const int h = blockIdx.y;
    const int l0 = blockIdx.x * 64;

    __shared__ __align__(16) float Hs[64][64];   // [s][d]
    __shared__ __align__(16) float Cs[64][68];   // [s][l] (transposed)

    const int tid = threadIdx.x;
    const int ty = tid >> 4, tx = tid & 15;

    {
        const float4* hsrc = (const float4*)(g_hstate + (size_t)(b * NH + h) * DST * HD);
        float4* hdst = (float4*)Hs;
#pragma unroll
        for (int i = 0; i < 4; i++) hdst[tid + i * 256] = hsrc[tid + i * 256];
    }
    {
        const int lr = tid >> 2;
        const int base = (tid & 3) * 4;
        const float* crow = g_xBCa + (size_t)(b * LL + l0 + lr) * CONVD + DINNER + DST;
#pragma unroll
        for (int it = 0; it < 4; it++) {
            const int sq = base + it * 16;
            float4 v = *(const float4*)(crow + sq);
            Cs[sq + 0][lr] = v.x; Cs[sq + 1][lr] = v.y;
            Cs[sq + 2][lr] = v.z; Cs[sq + 3][lr] = v.w;
        }
    }
    __syncthreads();

    float acc[4][4];
#pragma unroll
    for (int i = 0; i < 4; i++)
#pragma unroll
        for (int j = 0; j < 4; j++) acc[i][j] = 0.f;

#pragma unroll 16
    for (int s = 0; s < 64; s++) {
        float4 a = *(const float4*)&Cs[s][ty * 4];
        float4 hv = *(const float4*)&Hs[s][tx * 4];
        float av[4] = {a.x, a.y, a.z, a.w};
        float hvv[4] = {hv.x, hv.y, hv.z, hv.w};
#pragma unroll
        for (int i = 0; i < 4; i++)
#pragma unroll
            for (int j = 0; j < 4; j++)
                acc[i][j] = fmaf(av[i], hvv[j], acc[i][j]);
    }

    const float dcoef = Dp[h];
#pragma unroll
    for (int i = 0; i < 4; i++) {
        const int l = l0 + ty * 4 + i;
        const size_t r = (size_t)(b * LL + l);
#pragma unroll
        for (int j = 0; j < 4; j++) {
            const int d = tx * 4 + j;
            const int c = h * HD + d;
            const float xs = g_xBCa[r * CONVD + c];
            g_dx[r * DINNER + c] = acc[i][j] + xs * dcoef;  // y
        }
    }
}

// ---------------- g = y * silu(z); LayerNorm -> g_gn (tf32-rounded store) ----------------
__global__ void __launch_bounds__(256) ln_kernel(
    const float* __restrict__ nw, const float* __restrict__ nb)
{
    const int bl = blockIdx.x;
    const int tid = threadIdx.x;
    __shared__ float smu[8], sv[8];

    float v[3];
    float s = 0.f, s2 = 0.f;
#pragma unroll
    for (int i = 0; i < 3; i++) {
        const int c = tid + i * 256;
        const float y = g_dx[(size_t)bl * DINNER + c];
        const float z = g_z[(size_t)bl * DINNER + c];
        const float gg = y * (z / (1.f + expf(-z)));
        v[i] = gg;
        s += gg;
        s2 += gg * gg;
    }
#pragma unroll
    for (int o = 16; o > 0; o >>= 1) {
        s += __shfl_xor_sync(0xffffffffu, s, o);
        s2 += __shfl_xor_sync(0xffffffffu, s2, o);
    }
    const int w = tid >> 5;
    if ((tid & 31) == 0) { smu[w] = s; sv[w] = s2; }
    __syncthreads();
    float ts = 0.f, ts2 = 0.f;
#pragma unroll
    for (int i = 0; i < 8; i++) { ts += smu[i]; ts2 += sv[i]; }

    const float mu = ts * (1.f / (float)DINNER);
    const float var = ts2 * (1.f / (float)DINNER) - mu * mu;
    const float rstd = rsqrtf(var + 1e-5f);
#pragma unroll
    for (int i = 0; i < 3; i++) {
        const int c = tid + i * 256;
        const float o = (v[i] - mu) * rstd * nw[c] + nb[c];
        g_gn[(size_t)bl * DINNER + c] = __uint_as_float(f2tf32(o));
    }
}

// ---------------- launch ----------------
extern "C" void kernel_launch(void* const* d_in, const int* in_sizes, int n_in,
                              void* d_out, int out_size)
{
    const float* x    = (const float*)d_in[0];   // [BL, 384]
    const float* win  = (const float*)d_in[1];   // [1676, 384]
    const float* cw   = (const float*)d_in[2];   // [896, 1, 3, 3]
    const float* cb   = (const float*)d_in[3];   // [896]
    const float* dtb  = (const float*)d_in[4];   // [12]
    const float* alog = (const float*)d_in[5];   // [768]
    const float* Dp   = (const float*)d_in[6];   // [12]
    const float* nw   = (const float*)d_in[7];   // [768]
    const float* nb   = (const float*)d_in[8];   // [768]
    const float* wout = (const float*)d_in[9];   // [384, 768]
    float* out = (float*)d_out;                  // [BL, 384]

    cudaFuncSetAttribute(gemm_mma<DMODEL, 0>,
                         cudaFuncAttributeMaxDynamicSharedMemorySize, GEMM_DSMEM);
    cudaFuncSetAttribute(gemm_mma<DINNER, 1>,
                         cudaFuncAttributeMaxDynamicSharedMemorySize, GEMM_DSMEM);

    float* xcvt;    cudaGetSymbolAddress((void**)&xcvt, g_xcvt);
    float* wincvt;  cudaGetSymbolAddress((void**)&wincvt, g_wincvt);
    float* woutcvt; cudaGetSymbolAddress((void**)&woutcvt, g_woutcvt);

    // 1) zero h_state + tf32-round GEMM inputs (all independent)
    zero_hstate<<<384, 256>>>();
    cvt_kernel<<<(BL * DMODEL / 4 + 255) / 256, 256>>>(x, xcvt, BL * DMODEL / 4);
    cvt_kernel<<<(DPROJ * DMODEL / 4 + 255) / 256, 256>>>(win, wincvt, DPROJ * DMODEL / 4);
    cvt_kernel<<<(DMODEL * DINNER / 4 + 255) / 256, 256>>>(wout, woutcvt, DMODEL * DINNER / 4);
    // 2) in-proj GEMM (tf32 mma.sync + cp.async pipeline) + split epilogue
    gemm_mma<DMODEL, 0><<<dim3(14, 196), 256, GEMM_DSMEM>>>(nullptr, dtb, DPROJ);
    // 3) depthwise conv + silu, fused dx = act * dt * (-exp(A_log))
    conv_kernel<<<dim3(BL, 7), 128>>>(cw, cb, alog);
    // 4) 3x3 count-normalized avg pool
    pool_kernel<<<dim3(BL, 6), 128>>>();
    // 5) split-K batched state GEMM
    hstate_kernel<<<dim3(7, 12, 8), 256>>>();
    // 6) Ch + D*x -> y
    ch_kernel<<<dim3(49, 12, 8), 256>>>(Dp);
    // 7) gate + LayerNorm (stores tf32-rounded)
    ln_kernel<<<BL, 256>>>(nw, nb);
    // 8) out-proj GEMM
    gemm_mma<DINNER, 1><<<dim3(3, 196), 256, GEMM_DSMEM>>>(out, nullptr, DMODEL);
}